// round 6
// baseline (speedup 1.0000x reference)
#include <cuda_runtime.h>
#include <cuda_bf16.h>
#include <math.h>
#include <stdint.h>

#define BB 4
#define TT 90
#define FR (BB*TT)          // 360 frames
#define HW 224
#define DIN 256

// ---- scratch (device globals; no allocation) ----
__device__ __align__(16) uint32_t g_wB2[32*512];   // B fragments: bf16x2, swizzled
__device__ float g_biasf[64];
__device__ float g_pooled[FR*576];
__device__ float g_xm[FR*DIN];
__device__ float g_res[FR*DIN];
__device__ float g_u[FR*DIN];
__device__ float g_delta[FR*DIN];
__device__ float g_BC[FR*32];
__device__ float g_y[FR*DIN];

// ================= one-time weight prep =================
// B2 table: u32[kt2 32][n 64][q8 8], q8 XOR-swizzled by (((n>>2)&1)<<2).
// u32 (kt2,n,q8) = bf16x2 of BN-folded W[n][k], k = kt2*16 + q8*2 (+1).
// k -> s=k>>3 (tap slot), kx=k&7; real tap iff s<63 && kx<7.
__global__ void wfold_kernel(const float* __restrict__ conv_w,
                             const float* __restrict__ conv_b,
                             const float* __restrict__ gma,
                             const float* __restrict__ bta,
                             const float* __restrict__ mean,
                             const float* __restrict__ var)
{
    int idx = blockIdx.x * 256 + threadIdx.x;
    if (idx < 64) {
        float inv = gma[idx] * rsqrtf(var[idx] + 1e-5f);
        g_biasf[idx] = (conv_b[idx] - mean[idx]) * inv + bta[idx];
    }
    if (idx >= 32*512) return;
    int kt2 = idx >> 9; int rem = idx & 511;
    int n = rem >> 3;   int q8 = rem & 7;
    float inv = gma[n] * rsqrtf(var[n] + 1e-5f);
    float v[2];
    #pragma unroll
    for (int e = 0; e < 2; e++) {
        int k = kt2*16 + q8*2 + e;
        int s = k >> 3, kx = k & 7;
        float val = 0.f;
        if (s < 63 && kx < 7) {
            int p = s / 7, ky = s % 7;
            int kt = p / 3, c = p % 3;
            val = conv_w[(n*3 + c)*147 + kt*49 + ky*7 + kx] * inv;
        }
        v[e] = val;
    }
    __nv_bfloat162 pk = __floats2bfloat162_rn(v[0], v[1]);
    int q8s = q8 ^ (((n >> 2) & 1) << 2);
    g_wB2[kt2*512 + n*8 + q8s] = *(uint32_t*)&pk;
}

__global__ void zero_pooled_kernel(int off) {
    int i = off + blockIdx.x * 256 + threadIdx.x;
    if (i < FR*576) g_pooled[i] = 0.f;
}

// ================= conv via mma.sync (HMMA, tensor pipe) =================
// CTA = (frame, row-pair yp): D[M=128][N=64], M = y*64 + x (x<56 valid).
// Warp w: m-tiles {w (y=0), w+4 (y=1)}, all 8 n-tiles. 32 k-steps of 16.
// smem: s_in bf16 [99 rows][232] (45,936 B) | B2 64KB | s_pool 576 f32.
#define SIN_U32ROW 116
#define SMEM_B_OFF 45936
#define SMEM_POOL_OFF (45936 + 65536)
#define CONV_SMEM (SMEM_POOL_OFF + 576*4)   // 113,776 B

__device__ __forceinline__ void mma16816(float* c, const uint32_t* a,
                                         uint32_t b0, uint32_t b1) {
    asm volatile(
        "mma.sync.aligned.m16n8k16.row.col.f32.bf16.bf16.f32 "
        "{%0,%1,%2,%3}, {%4,%5,%6,%7}, {%8,%9}, {%0,%1,%2,%3};"
        : "+f"(c[0]), "+f"(c[1]), "+f"(c[2]), "+f"(c[3])
        : "r"(a[0]), "r"(a[1]), "r"(a[2]), "r"(a[3]), "r"(b0), "r"(b1));
}

__global__ __launch_bounds__(128, 2)
void conv_mma_kernel(const float* __restrict__ rgb)
{
    extern __shared__ char sm[];
    const uint32_t* in32 = (const uint32_t*)sm;
    const uint32_t* sB2  = (const uint32_t*)(sm + SMEM_B_OFF);
    float* s_pool        = (float*)(sm + SMEM_POOL_OFF);

    int blk = blockIdx.x;
    int yp = blk % 28; int frame = blk / 28;
    int t = frame % TT; int b = frame / TT;
    int tid = threadIdx.x;
    int w = tid >> 5; int lane = tid & 31;
    int g = lane >> 2; int q = lane & 3;

    for (int i = tid; i < 576; i += 128) s_pool[i] = 0.f;

    // ---- input patch: 9 planes x 11 rows, 114 u32 (228 bf16) per row ----
    int rowbase = 8*yp - 3;
    for (int r = w; r < 99; r += 4) {
        int pIdx = r / 11, iy = r % 11;
        int tin = t + pIdx/3 - 1; int c = pIdx % 3;
        int grow = rowbase + iy;
        bool rv = (tin >= 0) && (tin < TT) && (grow >= 0) && (grow < HW);
        const float* src = rgb + (((size_t)(b*TT + tin)*3 + c)*HW + grow)*HW;
        uint32_t* dst = (uint32_t*)sm + (pIdx*11 + iy)*SIN_U32ROW;
        #pragma unroll
        for (int it = 0; it < 4; it++) {
            int x2 = lane + it*32;
            if (x2 < 114) {
                int c0 = 2*x2 - 3, c1 = c0 + 1;
                float v0 = (rv && c0 >= 0 && c0 < HW) ? src[c0] : 0.f;
                float v1 = (rv && c1 >= 0 && c1 < HW) ? src[c1] : 0.f;
                __nv_bfloat162 pk = __floats2bfloat162_rn(v0, v1);
                dst[x2] = *(uint32_t*)&pk;
            }
        }
    }
    // ---- B table: 64KB verbatim (pre-swizzled) ----
    {
        const float4* ws = (const float4*)g_wB2;
        float4* wd = (float4*)(sm + SMEM_B_OFF);
        #pragma unroll
        for (int i = 0; i < 32; i++) wd[tid + i*128] = ws[tid + i*128];
    }
    __syncthreads();

    // per-thread A addressing
    int x_lo = w*16 + g;                       // always <= 55
    int x_hi = x_lo + 8; if (x_hi > 55) x_hi = 55;
    int blo = 2*x_lo + q;
    int bhi = 2*x_hi + q;
    int xor4 = ((g >> 2) & 1) << 2;
    int bq0 = q ^ xor4;

    float acc[2][8][4];
    #pragma unroll
    for (int y = 0; y < 2; y++)
        #pragma unroll
        for (int nt = 0; nt < 8; nt++)
            #pragma unroll
            for (int e = 0; e < 4; e++) acc[y][nt][e] = 0.f;

    #pragma unroll 1
    for (int kt2 = 0; kt2 < 32; kt2++) {
        int s0 = 2*kt2, s1 = s0 + 1;
        int p0 = s0 / 7, ky0 = s0 - 7*p0;
        int p1 = s1 / 7, ky1 = s1 - 7*p1;
        int o0 = (p0*11 + ky0)*SIN_U32ROW;
        int o1 = (p1*11 + ky1)*SIN_U32ROW;

        uint32_t a0[4], a1[4];
        a0[0] = in32[o0 + blo];        a0[1] = in32[o0 + bhi];
        a0[2] = in32[o1 + blo];        a0[3] = in32[o1 + bhi];
        a1[0] = in32[o0 + 464 + blo];  a1[1] = in32[o0 + 464 + bhi];
        a1[2] = in32[o1 + 464 + blo];  a1[3] = in32[o1 + 464 + bhi];

        const uint32_t* bb = sB2 + kt2*512 + g*8 + bq0;
        #pragma unroll
        for (int nt = 0; nt < 8; nt++) {
            uint32_t b0 = bb[nt*64];
            uint32_t b1 = bb[nt*64 + 4 - 2*(bq0 & 4)];   // = idx0 ^ 4
            mma16816(acc[0][nt], a0, b0, b1);
            mma16816(acc[1][nt], a1, b0, b1);
        }
    }

    // ---- epilogue: bias + exact GELU + pool bins (floor 18/19/19) ----
    const float i18 = 1.f/18.f, i19 = 1.f/19.f;
    #pragma unroll
    for (int y = 0; y < 2; y++) {
        int rowg = 2*yp + y;
        float rw = (rowg < 18) ? i18 : i19;
        int roff = (rowg < 18) ? 0 : ((rowg < 37) ? 3 : 6);
        #pragma unroll
        for (int h = 0; h < 2; h++) {
            int x = w*16 + g + h*8;
            if (x < 56) {
                int xbin = (x < 18) ? 0 : ((x < 37) ? 1 : 2);
                float cw = ((x < 18) ? i18 : i19) * rw;
                #pragma unroll
                for (int nt = 0; nt < 8; nt++) {
                    int ch0 = nt*8 + q*2;
                    float v0 = acc[y][nt][h*2]     + __ldg(g_biasf + ch0);
                    float v1 = acc[y][nt][h*2 + 1] + __ldg(g_biasf + ch0 + 1);
                    float g0 = 0.5f*v0*(1.0f + erff(v0*0.70710678118654752f));
                    float g1 = 0.5f*v1*(1.0f + erff(v1*0.70710678118654752f));
                    atomicAdd(&s_pool[ch0*9 + roff + xbin],       g0*cw);
                    atomicAdd(&s_pool[(ch0 + 1)*9 + roff + xbin], g1*cw);
                }
            }
        }
    }
    __syncthreads();
    int base = frame*576;
    for (int i = tid; i < 576; i += 128) atomicAdd(&g_pooled[base + i], s_pool[i]);
}

// ================= Mamba chain =================
__global__ void proj_inproj_kernel(const float* __restrict__ proj_w,
                                   const float* __restrict__ proj_b,
                                   const float* __restrict__ in_w)
{
    __shared__ float s_p[576];
    __shared__ float s_x[128];
    int pos = blockIdx.x;
    int tid = threadIdx.x;
    for (int i = tid; i < 576; i += 256) s_p[i] = g_pooled[pos*576 + i];
    __syncthreads();
    if (tid < 128) {
        float a = proj_b[tid];
        const float* wr = proj_w + tid*576;
        #pragma unroll 4
        for (int k = 0; k < 576; k++) a = fmaf(__ldg(wr + k), s_p[k], a);
        s_x[tid] = a;
    }
    __syncthreads();
    #pragma unroll
    for (int rr = 0; rr < 2; rr++) {
        int r = tid + rr*256;
        float a = 0.f;
        const float* wr = in_w + r*128;
        #pragma unroll 4
        for (int k = 0; k < 128; k++) a = fmaf(__ldg(wr + k), s_x[k], a);
        if (r < 256) g_xm[pos*256 + r] = a;
        else         g_res[pos*256 + (r-256)] = a;
    }
}

__global__ void conv1d_xproj_kernel(const float* __restrict__ cw,
                                    const float* __restrict__ cb,
                                    const float* __restrict__ xw,
                                    const float* __restrict__ dtw,
                                    const float* __restrict__ dtb)
{
    __shared__ float s_u[256];
    __shared__ float s_xd[40];
    int pos = blockIdx.x; int b = pos / TT; int l = pos % TT;
    int d = threadIdx.x;

    float xc = cb[d];
    #pragma unroll
    for (int k = 0; k < 4; k++) {
        int li = l - 3 + k;
        if (li >= 0) xc = fmaf(g_xm[(b*TT + li)*256 + d], cw[d*4 + k], xc);
    }
    float u = xc / (1.f + expf(-xc));
    s_u[d] = u;
    g_u[pos*256 + d] = u;
    __syncthreads();

    if (d < 40) {
        float a = 0.f;
        const float* wr = xw + d*256;
        #pragma unroll 4
        for (int k = 0; k < 256; k++) a = fmaf(__ldg(wr + k), s_u[k], a);
        s_xd[d] = a;
    }
    __syncthreads();

    float dr = dtb[d];
    #pragma unroll
    for (int k = 0; k < 8; k++) dr = fmaf(dtw[d*8 + k], s_xd[k], dr);
    float delta = (dr > 20.f) ? dr : log1pf(expf(dr));
    g_delta[pos*256 + d] = delta;
    if (d < 32) g_BC[pos*32 + d] = s_xd[8 + d];
}

__global__ void scan_kernel(const float* __restrict__ A_log,
                            const float* __restrict__ Dp)
{
    int b = blockIdx.x >> 3;
    int d = ((blockIdx.x & 7) << 5) + threadIdx.x;
    float A[16], h[16];
    #pragma unroll
    for (int n = 0; n < 16; n++) { A[n] = -expf(A_log[d*16 + n]); h[n] = 0.f; }
    float Dd = Dp[d];

    for (int l = 0; l < TT; l++) {
        int pos = b*TT + l;
        float delta = g_delta[pos*256 + d];
        float u     = g_u[pos*256 + d];
        float res   = g_res[pos*256 + d];
        const float* BC = g_BC + pos*32;
        float du = delta * u;
        float y = 0.f;
        #pragma unroll
        for (int n = 0; n < 16; n++) {
            float dA = expf(delta * A[n]);
            h[n] = fmaf(dA, h[n], du * __ldg(BC + n));
            y = fmaf(h[n], __ldg(BC + 16 + n), y);
        }
        y = fmaf(u, Dd, y);
        y *= res / (1.f + expf(-res));
        g_y[pos*256 + d] = y;
    }
}

__global__ void outproj_kernel(const float* __restrict__ ow,
                               float* __restrict__ out)
{
    __shared__ float s_y[256];
    int pos = blockIdx.x;
    int tid = threadIdx.x;
    s_y[tid]       = g_y[pos*256 + tid];
    s_y[tid + 128] = g_y[pos*256 + tid + 128];
    __syncthreads();
    float a = 0.f;
    const float* wr = ow + tid*256;
    #pragma unroll 4
    for (int k = 0; k < 256; k++) a = fmaf(__ldg(wr + k), s_y[k], a);
    out[pos*128 + tid] = a;
}

// ============================================================
extern "C" void kernel_launch(void* const* d_in, const int* in_sizes, int n_in,
                              void* d_out, int out_size)
{
    (void)in_sizes; (void)n_in; (void)out_size;
    const float* rgb     = (const float*)d_in[0];
    const float* conv_w  = (const float*)d_in[1];
    const float* conv_b  = (const float*)d_in[2];
    const float* bn_g    = (const float*)d_in[3];
    const float* bn_b    = (const float*)d_in[4];
    const float* bn_m    = (const float*)d_in[5];
    const float* bn_v    = (const float*)d_in[6];
    const float* proj_w  = (const float*)d_in[7];
    const float* proj_b  = (const float*)d_in[8];
    const float* m_in_w  = (const float*)d_in[9];
    const float* m_cw    = (const float*)d_in[10];
    const float* m_cb    = (const float*)d_in[11];
    const float* m_xw    = (const float*)d_in[12];
    const float* m_dtw   = (const float*)d_in[13];
    const float* m_dtb   = (const float*)d_in[14];
    const float* m_Alog  = (const float*)d_in[15];
    const float* m_D     = (const float*)d_in[16];
    const float* m_ow    = (const float*)d_in[17];
    float* out = (float*)d_out;

    cudaFuncSetAttribute(conv_mma_kernel,
                         cudaFuncAttributeMaxDynamicSharedMemorySize, CONV_SMEM);

    // wfold + 2 zeros position conv at ncu launch index 5 (as in R4)
    wfold_kernel<<<(32*512 + 255)/256, 256>>>(conv_w, conv_b, bn_g, bn_b, bn_m, bn_v);
    const int H = (FR*576) / 2;
    zero_pooled_kernel<<<(H + 255)/256, 256>>>(0);
    zero_pooled_kernel<<<(H + 255)/256, 256>>>(H);

    conv_mma_kernel<<<FR*28, 128, CONV_SMEM>>>(rgb);

    proj_inproj_kernel<<<FR, 256>>>(proj_w, proj_b, m_in_w);
    conv1d_xproj_kernel<<<FR, 256>>>(m_cw, m_cb, m_xw, m_dtw, m_dtb);
    scan_kernel<<<32, 32>>>(m_Alog, m_D);
    outproj_kernel<<<FR, 128>>>(m_ow, out);
}

// round 8
// speedup vs baseline: 1.6467x; 1.6467x over previous
#include <cuda_runtime.h>
#include <cuda_bf16.h>
#include <math.h>
#include <stdint.h>

#define BB 4
#define TT 90
#define FR (BB*TT)          // 360 frames
#define HW 224
#define DIN 256

// ---- scratch (device globals; no allocation) ----
__device__ __align__(16) uint4 g_wBv[32*4*32];     // B frags: [kt2][j][lane], 64KB
__device__ float g_biasf[64];
__device__ float g_pooled[FR*576];
__device__ float g_xm[FR*DIN];
__device__ float g_res[FR*DIN];
__device__ float g_u[FR*DIN];
__device__ float g_delta[FR*DIN];
__device__ float g_BC[FR*32];
__device__ float g_y[FR*DIN];

// ================= one-time weight prep =================
// g_wBv[kt2][j][lane] uint4; comp c: nt = 2j + (c>>1), h = c&1.
// value = bf16x2( W[n][k], W[n][k+1] ) BN-folded,
//   n = nt*8 + lane/4,  k = kt2*16 + h*8 + (lane%4)*2.
// k -> s = k>>3 (tap slot), kx = k&7; real tap iff s<63 && kx<7.
__global__ void wfold_kernel(const float* __restrict__ conv_w,
                             const float* __restrict__ conv_b,
                             const float* __restrict__ gma,
                             const float* __restrict__ bta,
                             const float* __restrict__ mean,
                             const float* __restrict__ var)
{
    int idx = blockIdx.x * 256 + threadIdx.x;
    if (idx < 64) {
        float inv = gma[idx] * rsqrtf(var[idx] + 1e-5f);
        g_biasf[idx] = (conv_b[idx] - mean[idx]) * inv + bta[idx];
    }
    if (idx >= 32*4*32) return;
    int kt2  = idx >> 7;
    int j    = (idx >> 5) & 3;
    int lane = idx & 31;
    uint32_t comp[4];
    #pragma unroll
    for (int c = 0; c < 4; c++) {
        int nt = 2*j + (c >> 1); int h = c & 1;
        int n = nt*8 + (lane >> 2);
        int kbase = kt2*16 + h*8 + (lane & 3)*2;
        float inv = gma[n] * rsqrtf(var[n] + 1e-5f);
        float v[2];
        #pragma unroll
        for (int e = 0; e < 2; e++) {
            int k = kbase + e;
            int s = k >> 3, kx = k & 7;
            float val = 0.f;
            if (s < 63 && kx < 7) {
                int p = s / 7, ky = s % 7;
                int kt = p / 3, cc = p % 3;
                val = conv_w[(n*3 + cc)*147 + kt*49 + ky*7 + kx] * inv;
            }
            v[e] = val;
        }
        __nv_bfloat162 pk = __floats2bfloat162_rn(v[0], v[1]);
        comp[c] = *(uint32_t*)&pk;
    }
    g_wBv[idx] = make_uint4(comp[0], comp[1], comp[2], comp[3]);
}

__global__ void zero_pooled_kernel(int off) {
    int i = off + blockIdx.x * 256 + threadIdx.x;
    if (i < FR*576) g_pooled[i] = 0.f;
}

// ================= conv via mma.sync (HMMA) =================
// CTA = (frame, row-pair yp): D[M=128][N=64], M = y*64 + x (x<56 valid).
// Warp w: m-tiles {w (y=0), w+4 (y=1)}, all 8 n-tiles, 32 k-steps of 16.
// A from smem input patch (LDS.32), B from gmem frag table (LDG.128).
// smem: s_in bf16 [99 rows][232] (45,936 B) | s_pool 576 f32.  48,240 B total.
#define SIN_U32ROW 116
#define SMEM_POOL_OFF 45936
#define CONV_SMEM (SMEM_POOL_OFF + 576*4)   // 48,240 B -> 4 CTAs/SM

__device__ __forceinline__ void mma16816(float* c, const uint32_t* a,
                                         uint32_t b0, uint32_t b1) {
    asm volatile(
        "mma.sync.aligned.m16n8k16.row.col.f32.bf16.bf16.f32 "
        "{%0,%1,%2,%3}, {%4,%5,%6,%7}, {%8,%9}, {%0,%1,%2,%3};"
        : "+f"(c[0]), "+f"(c[1]), "+f"(c[2]), "+f"(c[3])
        : "r"(a[0]), "r"(a[1]), "r"(a[2]), "r"(a[3]), "r"(b0), "r"(b1));
}

__global__ __launch_bounds__(128, 4)
void conv_mma_kernel(const float* __restrict__ rgb)
{
    extern __shared__ char sm[];
    const uint32_t* in32 = (const uint32_t*)sm;
    float* s_pool        = (float*)(sm + SMEM_POOL_OFF);

    int blk = blockIdx.x;
    int yp = blk % 28; int frame = blk / 28;
    int t = frame % TT; int b = frame / TT;
    int tid = threadIdx.x;
    int w = tid >> 5; int lane = tid & 31;
    int g = lane >> 2; int q = lane & 3;

    for (int i = tid; i < 576; i += 128) s_pool[i] = 0.f;

    // ---- input patch: 9 planes x 11 rows, 114 u32 (228 bf16) per row ----
    int rowbase = 8*yp - 3;
    for (int r = w; r < 99; r += 4) {
        int pIdx = r / 11, iy = r % 11;
        int tin = t + pIdx/3 - 1; int c = pIdx % 3;
        int grow = rowbase + iy;
        bool rv = (tin >= 0) && (tin < TT) && (grow >= 0) && (grow < HW);
        const float* src = rgb + (((size_t)(b*TT + tin)*3 + c)*HW + grow)*HW;
        uint32_t* dst = (uint32_t*)sm + (pIdx*11 + iy)*SIN_U32ROW;
        #pragma unroll
        for (int it = 0; it < 4; it++) {
            int x2 = lane + it*32;
            if (x2 < 114) {
                int c0 = 2*x2 - 3, c1 = c0 + 1;
                float v0 = (rv && c0 >= 0 && c0 < HW) ? src[c0] : 0.f;
                float v1 = (rv && c1 >= 0 && c1 < HW) ? src[c1] : 0.f;
                __nv_bfloat162 pk = __floats2bfloat162_rn(v0, v1);
                dst[x2] = *(uint32_t*)&pk;
            }
        }
    }
    __syncthreads();

    // per-thread A addressing (validated fragment mapping, R6)
    int x_lo = w*16 + g;                       // <= 55 always
    int x_hi = x_lo + 8; if (x_hi > 55) x_hi = 55;
    int blo = 2*x_lo + q;
    int bhi = 2*x_hi + q;

    float acc[2][8][4];
    #pragma unroll
    for (int y = 0; y < 2; y++)
        #pragma unroll
        for (int nt = 0; nt < 8; nt++)
            #pragma unroll
            for (int e = 0; e < 4; e++) acc[y][nt][e] = 0.f;

    const uint4* btab = g_wBv + lane;

    #pragma unroll
    for (int kt2 = 0; kt2 < 32; kt2++) {
        const int s0 = 2*kt2, s1 = s0 + 1;
        const int p0 = s0 / 7, ky0 = s0 - 7*p0;
        const int p1 = s1 / 7, ky1 = s1 - 7*p1;
        const int o0 = (p0*11 + ky0)*SIN_U32ROW;
        // s1==63 is the zero-weight pad slot: clamp to a VALID smem row.
        // (Weights are zero, but garbage beyond the patch can decode as
        //  bf16 NaN and NaN*0 = NaN — this was the R7 failure.)
        const int o1 = (s1 == 63) ? o0 : (p1*11 + ky1)*SIN_U32ROW;

        uint4 B0 = __ldg(btab + kt2*128);
        uint4 B1 = __ldg(btab + kt2*128 + 32);
        uint4 B2 = __ldg(btab + kt2*128 + 64);
        uint4 B3 = __ldg(btab + kt2*128 + 96);

        uint32_t a0[4], a1[4];
        a0[0] = in32[o0 + blo];        a0[1] = in32[o0 + bhi];
        a0[2] = in32[o1 + blo];        a0[3] = in32[o1 + bhi];
        a1[0] = in32[o0 + 464 + blo];  a1[1] = in32[o0 + 464 + bhi];
        a1[2] = in32[o1 + 464 + blo];  a1[3] = in32[o1 + 464 + bhi];

        mma16816(acc[0][0], a0, B0.x, B0.y);  mma16816(acc[1][0], a1, B0.x, B0.y);
        mma16816(acc[0][1], a0, B0.z, B0.w);  mma16816(acc[1][1], a1, B0.z, B0.w);
        mma16816(acc[0][2], a0, B1.x, B1.y);  mma16816(acc[1][2], a1, B1.x, B1.y);
        mma16816(acc[0][3], a0, B1.z, B1.w);  mma16816(acc[1][3], a1, B1.z, B1.w);
        mma16816(acc[0][4], a0, B2.x, B2.y);  mma16816(acc[1][4], a1, B2.x, B2.y);
        mma16816(acc[0][5], a0, B2.z, B2.w);  mma16816(acc[1][5], a1, B2.z, B2.w);
        mma16816(acc[0][6], a0, B3.x, B3.y);  mma16816(acc[1][6], a1, B3.x, B3.y);
        mma16816(acc[0][7], a0, B3.z, B3.w);  mma16816(acc[1][7], a1, B3.z, B3.w);
    }

    // ---- epilogue: bias + exact GELU + pool bins (floor 18/19/19) ----
    const float i18 = 1.f/18.f, i19 = 1.f/19.f;
    #pragma unroll
    for (int y = 0; y < 2; y++) {
        int rowg = 2*yp + y;
        float rw = (rowg < 18) ? i18 : i19;
        int roff = (rowg < 18) ? 0 : ((rowg < 37) ? 3 : 6);
        #pragma unroll
        for (int h = 0; h < 2; h++) {
            int x = w*16 + g + h*8;
            if (x < 56) {
                int xbin = (x < 18) ? 0 : ((x < 37) ? 1 : 2);
                float cw = ((x < 18) ? i18 : i19) * rw;
                #pragma unroll
                for (int nt = 0; nt < 8; nt++) {
                    int ch0 = nt*8 + q*2;
                    float v0 = acc[y][nt][h*2]     + __ldg(g_biasf + ch0);
                    float v1 = acc[y][nt][h*2 + 1] + __ldg(g_biasf + ch0 + 1);
                    float g0 = 0.5f*v0*(1.0f + erff(v0*0.70710678118654752f));
                    float g1 = 0.5f*v1*(1.0f + erff(v1*0.70710678118654752f));
                    atomicAdd(&s_pool[ch0*9 + roff + xbin],       g0*cw);
                    atomicAdd(&s_pool[(ch0 + 1)*9 + roff + xbin], g1*cw);
                }
            }
        }
    }
    __syncthreads();
    int base = frame*576;
    for (int i = tid; i < 576; i += 128) atomicAdd(&g_pooled[base + i], s_pool[i]);
}

// ================= Mamba chain =================
__global__ void proj_inproj_kernel(const float* __restrict__ proj_w,
                                   const float* __restrict__ proj_b,
                                   const float* __restrict__ in_w)
{
    __shared__ float s_p[576];
    __shared__ float s_x[128];
    int pos = blockIdx.x;
    int tid = threadIdx.x;
    for (int i = tid; i < 576; i += 256) s_p[i] = g_pooled[pos*576 + i];
    __syncthreads();
    if (tid < 128) {
        float a = proj_b[tid];
        const float* wr = proj_w + tid*576;
        #pragma unroll 4
        for (int k = 0; k < 576; k++) a = fmaf(__ldg(wr + k), s_p[k], a);
        s_x[tid] = a;
    }
    __syncthreads();
    #pragma unroll
    for (int rr = 0; rr < 2; rr++) {
        int r = tid + rr*256;
        float a = 0.f;
        const float* wr = in_w + r*128;
        #pragma unroll 4
        for (int k = 0; k < 128; k++) a = fmaf(__ldg(wr + k), s_x[k], a);
        if (r < 256) g_xm[pos*256 + r] = a;
        else         g_res[pos*256 + (r-256)] = a;
    }
}

__global__ void conv1d_xproj_kernel(const float* __restrict__ cw,
                                    const float* __restrict__ cb,
                                    const float* __restrict__ xw,
                                    const float* __restrict__ dtw,
                                    const float* __restrict__ dtb)
{
    __shared__ float s_u[256];
    __shared__ float s_xd[40];
    int pos = blockIdx.x; int b = pos / TT; int l = pos % TT;
    int d = threadIdx.x;

    float xc = cb[d];
    #pragma unroll
    for (int k = 0; k < 4; k++) {
        int li = l - 3 + k;
        if (li >= 0) xc = fmaf(g_xm[(b*TT + li)*256 + d], cw[d*4 + k], xc);
    }
    float u = xc / (1.f + expf(-xc));
    s_u[d] = u;
    g_u[pos*256 + d] = u;
    __syncthreads();

    if (d < 40) {
        float a = 0.f;
        const float* wr = xw + d*256;
        #pragma unroll 4
        for (int k = 0; k < 256; k++) a = fmaf(__ldg(wr + k), s_u[k], a);
        s_xd[d] = a;
    }
    __syncthreads();

    float dr = dtb[d];
    #pragma unroll
    for (int k = 0; k < 8; k++) dr = fmaf(dtw[d*8 + k], s_xd[k], dr);
    float delta = (dr > 20.f) ? dr : log1pf(expf(dr));
    g_delta[pos*256 + d] = delta;
    if (d < 32) g_BC[pos*32 + d] = s_xd[8 + d];
}

__global__ void scan_kernel(const float* __restrict__ A_log,
                            const float* __restrict__ Dp)
{
    int b = blockIdx.x >> 3;
    int d = ((blockIdx.x & 7) << 5) + threadIdx.x;
    float A[16], h[16];
    #pragma unroll
    for (int n = 0; n < 16; n++) { A[n] = -expf(A_log[d*16 + n]); h[n] = 0.f; }
    float Dd = Dp[d];

    for (int l = 0; l < TT; l++) {
        int pos = b*TT + l;
        float delta = g_delta[pos*256 + d];
        float u     = g_u[pos*256 + d];
        float res   = g_res[pos*256 + d];
        const float* BC = g_BC + pos*32;
        float du = delta * u;
        float y = 0.f;
        #pragma unroll
        for (int n = 0; n < 16; n++) {
            float dA = expf(delta * A[n]);
            h[n] = fmaf(dA, h[n], du * __ldg(BC + n));
            y = fmaf(h[n], __ldg(BC + 16 + n), y);
        }
        y = fmaf(u, Dd, y);
        y *= res / (1.f + expf(-res));
        g_y[pos*256 + d] = y;
    }
}

__global__ void outproj_kernel(const float* __restrict__ ow,
                               float* __restrict__ out)
{
    __shared__ float s_y[256];
    int pos = blockIdx.x;
    int tid = threadIdx.x;
    s_y[tid]       = g_y[pos*256 + tid];
    s_y[tid + 128] = g_y[pos*256 + tid + 128];
    __syncthreads();
    float a = 0.f;
    const float* wr = ow + tid*256;
    #pragma unroll 4
    for (int k = 0; k < 256; k++) a = fmaf(__ldg(wr + k), s_y[k], a);
    out[pos*128 + tid] = a;
}

// ============================================================
extern "C" void kernel_launch(void* const* d_in, const int* in_sizes, int n_in,
                              void* d_out, int out_size)
{
    (void)in_sizes; (void)n_in; (void)out_size;
    const float* rgb     = (const float*)d_in[0];
    const float* conv_w  = (const float*)d_in[1];
    const float* conv_b  = (const float*)d_in[2];
    const float* bn_g    = (const float*)d_in[3];
    const float* bn_b    = (const float*)d_in[4];
    const float* bn_m    = (const float*)d_in[5];
    const float* bn_v    = (const float*)d_in[6];
    const float* proj_w  = (const float*)d_in[7];
    const float* proj_b  = (const float*)d_in[8];
    const float* m_in_w  = (const float*)d_in[9];
    const float* m_cw    = (const float*)d_in[10];
    const float* m_cb    = (const float*)d_in[11];
    const float* m_xw    = (const float*)d_in[12];
    const float* m_dtw   = (const float*)d_in[13];
    const float* m_dtb   = (const float*)d_in[14];
    const float* m_Alog  = (const float*)d_in[15];
    const float* m_D     = (const float*)d_in[16];
    const float* m_ow    = (const float*)d_in[17];
    float* out = (float*)d_out;

    cudaFuncSetAttribute(conv_mma_kernel,
                         cudaFuncAttributeMaxDynamicSharedMemorySize, CONV_SMEM);

    // wfold + 2 zeros position conv at ncu launch index 5
    wfold_kernel<<<(32*4*32 + 255)/256, 256>>>(conv_w, conv_b, bn_g, bn_b, bn_m, bn_v);
    const int H = (FR*576) / 2;
    zero_pooled_kernel<<<(H + 255)/256, 256>>>(0);
    zero_pooled_kernel<<<(H + 255)/256, 256>>>(H);

    conv_mma_kernel<<<FR*28, 128, CONV_SMEM>>>(rgb);

    proj_inproj_kernel<<<FR, 256>>>(proj_w, proj_b, m_in_w);
    conv1d_xproj_kernel<<<FR, 256>>>(m_cw, m_cb, m_xw, m_dtw, m_dtb);
    scan_kernel<<<32, 32>>>(m_Alog, m_D);
    outproj_kernel<<<FR, 128>>>(m_ow, out);
}

// round 9
// speedup vs baseline: 2.2053x; 1.3392x over previous
#include <cuda_runtime.h>
#include <cuda_bf16.h>
#include <math.h>
#include <stdint.h>

#define BB 4
#define TT 90
#define FR (BB*TT)          // 360 frames
#define HW 224
#define DIN 256

// ---- scratch (device globals; no allocation) ----
__device__ __align__(16) uint4 g_wBv[32*4*32];     // B frags: [kt2][j][lane], 64KB
__device__ float g_biasf[64];
__device__ float g_pooled[FR*576];
__device__ float g_xm[FR*DIN];
__device__ float g_res[FR*DIN];
__device__ float g_u[FR*DIN];
__device__ float g_delta[FR*DIN];
__device__ __align__(16) float g_BC[FR*32];
__device__ float g_y[FR*DIN];

// ================= one-time weight prep =================
// g_wBv[kt2][j][lane] uint4; comp c: nt = 2j + (c>>1), h = c&1.
// value = bf16x2( W[n][k], W[n][k+1] ) BN-folded,
//   n = nt*8 + lane/4,  k = kt2*16 + h*8 + (lane%4)*2.
// k -> s = k>>3 (tap slot), kx = k&7; real tap iff s<63 && kx<7.
__global__ void wfold_kernel(const float* __restrict__ conv_w,
                             const float* __restrict__ conv_b,
                             const float* __restrict__ gma,
                             const float* __restrict__ bta,
                             const float* __restrict__ mean,
                             const float* __restrict__ var)
{
    int idx = blockIdx.x * 256 + threadIdx.x;
    if (idx < 64) {
        float inv = gma[idx] * rsqrtf(var[idx] + 1e-5f);
        g_biasf[idx] = (conv_b[idx] - mean[idx]) * inv + bta[idx];
    }
    if (idx >= 32*4*32) return;
    int kt2  = idx >> 7;
    int j    = (idx >> 5) & 3;
    int lane = idx & 31;
    uint32_t comp[4];
    #pragma unroll
    for (int c = 0; c < 4; c++) {
        int nt = 2*j + (c >> 1); int h = c & 1;
        int n = nt*8 + (lane >> 2);
        int kbase = kt2*16 + h*8 + (lane & 3)*2;
        float inv = gma[n] * rsqrtf(var[n] + 1e-5f);
        float v[2];
        #pragma unroll
        for (int e = 0; e < 2; e++) {
            int k = kbase + e;
            int s = k >> 3, kx = k & 7;
            float val = 0.f;
            if (s < 63 && kx < 7) {
                int p = s / 7, ky = s % 7;
                int kt = p / 3, cc = p % 3;
                val = conv_w[(n*3 + cc)*147 + kt*49 + ky*7 + kx] * inv;
            }
            v[e] = val;
        }
        __nv_bfloat162 pk = __floats2bfloat162_rn(v[0], v[1]);
        comp[c] = *(uint32_t*)&pk;
    }
    g_wBv[idx] = make_uint4(comp[0], comp[1], comp[2], comp[3]);
}

__global__ void zero_pooled_kernel(int off) {
    int i = off + blockIdx.x * 256 + threadIdx.x;
    if (i < FR*576) g_pooled[i] = 0.f;
}

// ================= conv via mma.sync (HMMA) =================
// CTA = (frame, row-pair yp): D[M=128][N=64], M = y*64 + x (x<56 valid).
// 256 threads / 8 warps. Warp w = (m-pair w&3, n-half w>>2):
//   m-tiles {w&3 (y=0), (w&3)+4 (y=1)}, n-tiles (w>>2)*4 .. +3, 32 k-steps.
// A from smem input patch (LDS.32), B from gmem frag table (LDG.128).
// smem: s_in bf16 [99 rows][232] (45,936 B) | s_pool 576 f32.  48,240 B.
#define SIN_U32ROW 116
#define SMEM_POOL_OFF 45936
#define CONV_SMEM (SMEM_POOL_OFF + 576*4)   // 48,240 B -> 4 CTAs/SM

__device__ __forceinline__ void mma16816(float* c, const uint32_t* a,
                                         uint32_t b0, uint32_t b1) {
    asm volatile(
        "mma.sync.aligned.m16n8k16.row.col.f32.bf16.bf16.f32 "
        "{%0,%1,%2,%3}, {%4,%5,%6,%7}, {%8,%9}, {%0,%1,%2,%3};"
        : "+f"(c[0]), "+f"(c[1]), "+f"(c[2]), "+f"(c[3])
        : "r"(a[0]), "r"(a[1]), "r"(a[2]), "r"(a[3]), "r"(b0), "r"(b1));
}

__global__ __launch_bounds__(256, 4)
void conv_mma_kernel(const float* __restrict__ rgb)
{
    extern __shared__ char sm[];
    const uint32_t* in32 = (const uint32_t*)sm;
    float* s_pool        = (float*)(sm + SMEM_POOL_OFF);

    int blk = blockIdx.x;
    int yp = blk % 28; int frame = blk / 28;
    int t = frame % TT; int b = frame / TT;
    int tid = threadIdx.x;
    int w = tid >> 5; int lane = tid & 31;
    int g = lane >> 2; int q = lane & 3;
    int wm = w & 3;    int nh = w >> 2;

    for (int i = tid; i < 576; i += 256) s_pool[i] = 0.f;

    // ---- input patch: 9 planes x 11 rows, 114 u32 (228 bf16) per row ----
    int rowbase = 8*yp - 3;
    for (int r = w; r < 99; r += 8) {
        int pIdx = r / 11, iy = r % 11;
        int tin = t + pIdx/3 - 1; int c = pIdx % 3;
        int grow = rowbase + iy;
        bool rv = (tin >= 0) && (tin < TT) && (grow >= 0) && (grow < HW);
        const float* src = rgb + (((size_t)(b*TT + tin)*3 + c)*HW + grow)*HW;
        uint32_t* dst = (uint32_t*)sm + (pIdx*11 + iy)*SIN_U32ROW;
        #pragma unroll
        for (int it = 0; it < 4; it++) {
            int x2 = lane + it*32;
            if (x2 < 114) {
                int c0 = 2*x2 - 3, c1 = c0 + 1;
                float v0 = (rv && c0 >= 0 && c0 < HW) ? src[c0] : 0.f;
                float v1 = (rv && c1 >= 0 && c1 < HW) ? src[c1] : 0.f;
                __nv_bfloat162 pk = __floats2bfloat162_rn(v0, v1);
                dst[x2] = *(uint32_t*)&pk;
            }
        }
    }
    __syncthreads();

    // per-thread A addressing (validated fragment mapping, R6)
    int x_lo = wm*16 + g;                      // <= 55 always
    int x_hi = x_lo + 8; if (x_hi > 55) x_hi = 55;
    int blo = 2*x_lo + q;
    int bhi = 2*x_hi + q;

    float acc[2][4][4];
    #pragma unroll
    for (int y = 0; y < 2; y++)
        #pragma unroll
        for (int nt = 0; nt < 4; nt++)
            #pragma unroll
            for (int e = 0; e < 4; e++) acc[y][nt][e] = 0.f;

    const uint4* btab = g_wBv + nh*64 + lane;   // j base = nh*2

    #pragma unroll
    for (int kt2 = 0; kt2 < 32; kt2++) {
        const int s0 = 2*kt2, s1 = s0 + 1;
        const int p0 = s0 / 7, ky0 = s0 - 7*p0;
        const int p1 = s1 / 7, ky1 = s1 - 7*p1;
        const int o0 = (p0*11 + ky0)*SIN_U32ROW;
        // s1==63 is the zero-weight pad slot: clamp to a VALID smem row
        // (garbage beyond the patch can decode as bf16 NaN; NaN*0=NaN).
        const int o1 = (s1 == 63) ? o0 : (p1*11 + ky1)*SIN_U32ROW;

        uint4 B0 = __ldg(btab + kt2*128);
        uint4 B1 = __ldg(btab + kt2*128 + 32);

        uint32_t a0[4], a1[4];
        a0[0] = in32[o0 + blo];        a0[1] = in32[o0 + bhi];
        a0[2] = in32[o1 + blo];        a0[3] = in32[o1 + bhi];
        a1[0] = in32[o0 + 464 + blo];  a1[1] = in32[o0 + 464 + bhi];
        a1[2] = in32[o1 + 464 + blo];  a1[3] = in32[o1 + 464 + bhi];

        mma16816(acc[0][0], a0, B0.x, B0.y);  mma16816(acc[1][0], a1, B0.x, B0.y);
        mma16816(acc[0][1], a0, B0.z, B0.w);  mma16816(acc[1][1], a1, B0.z, B0.w);
        mma16816(acc[0][2], a0, B1.x, B1.y);  mma16816(acc[1][2], a1, B1.x, B1.y);
        mma16816(acc[0][3], a0, B1.z, B1.w);  mma16816(acc[1][3], a1, B1.z, B1.w);
    }

    // ---- epilogue: bias + exact GELU + pool bins (floor 18/19/19) ----
    const float i18 = 1.f/18.f, i19 = 1.f/19.f;
    #pragma unroll
    for (int y = 0; y < 2; y++) {
        int rowg = 2*yp + y;
        float rw = (rowg < 18) ? i18 : i19;
        int roff = (rowg < 18) ? 0 : ((rowg < 37) ? 3 : 6);
        #pragma unroll
        for (int h = 0; h < 2; h++) {
            int x = wm*16 + g + h*8;
            if (x < 56) {
                int xbin = (x < 18) ? 0 : ((x < 37) ? 1 : 2);
                float cw = ((x < 18) ? i18 : i19) * rw;
                #pragma unroll
                for (int nt = 0; nt < 4; nt++) {
                    int ch0 = (nh*4 + nt)*8 + q*2;
                    float v0 = acc[y][nt][h*2]     + __ldg(g_biasf + ch0);
                    float v1 = acc[y][nt][h*2 + 1] + __ldg(g_biasf + ch0 + 1);
                    float g0 = 0.5f*v0*(1.0f + erff(v0*0.70710678118654752f));
                    float g1 = 0.5f*v1*(1.0f + erff(v1*0.70710678118654752f));
                    atomicAdd(&s_pool[ch0*9 + roff + xbin],       g0*cw);
                    atomicAdd(&s_pool[(ch0 + 1)*9 + roff + xbin], g1*cw);
                }
            }
        }
    }
    __syncthreads();
    int base = frame*576;
    for (int i = tid; i < 576; i += 256) atomicAdd(&g_pooled[base + i], s_pool[i]);
}

// ================= Mamba chain =================
__global__ void proj_inproj_kernel(const float* __restrict__ proj_w,
                                   const float* __restrict__ proj_b,
                                   const float* __restrict__ in_w)
{
    __shared__ float s_p[576];
    __shared__ float s_x[128];
    int pos = blockIdx.x;
    int tid = threadIdx.x;
    for (int i = tid; i < 576; i += 256) s_p[i] = g_pooled[pos*576 + i];
    __syncthreads();
    if (tid < 128) {
        float a = proj_b[tid];
        const float* wr = proj_w + tid*576;
        #pragma unroll 4
        for (int k = 0; k < 576; k++) a = fmaf(__ldg(wr + k), s_p[k], a);
        s_x[tid] = a;
    }
    __syncthreads();
    #pragma unroll
    for (int rr = 0; rr < 2; rr++) {
        int r = tid + rr*256;
        float a = 0.f;
        const float* wr = in_w + r*128;
        #pragma unroll 4
        for (int k = 0; k < 128; k++) a = fmaf(__ldg(wr + k), s_x[k], a);
        if (r < 256) g_xm[pos*256 + r] = a;
        else         g_res[pos*256 + (r-256)] = a;
    }
}

__global__ void conv1d_xproj_kernel(const float* __restrict__ cw,
                                    const float* __restrict__ cb,
                                    const float* __restrict__ xw,
                                    const float* __restrict__ dtw,
                                    const float* __restrict__ dtb)
{
    __shared__ float s_u[256];
    __shared__ float s_xd[40];
    int pos = blockIdx.x; int b = pos / TT; int l = pos % TT;
    int d = threadIdx.x;

    float xc = cb[d];
    #pragma unroll
    for (int k = 0; k < 4; k++) {
        int li = l - 3 + k;
        if (li >= 0) xc = fmaf(g_xm[(b*TT + li)*256 + d], cw[d*4 + k], xc);
    }
    float u = xc / (1.f + expf(-xc));
    s_u[d] = u;
    g_u[pos*256 + d] = u;
    __syncthreads();

    if (d < 40) {
        float a = 0.f;
        const float* wr = xw + d*256;
        #pragma unroll 4
        for (int k = 0; k < 256; k++) a = fmaf(__ldg(wr + k), s_u[k], a);
        s_xd[d] = a;
    }
    __syncthreads();

    float dr = dtb[d];
    #pragma unroll
    for (int k = 0; k < 8; k++) dr = fmaf(dtw[d*8 + k], s_xd[k], dr);
    float delta = (dr > 20.f) ? dr : log1pf(expf(dr));
    g_delta[pos*256 + d] = delta;
    if (d < 32) g_BC[pos*32 + d] = s_xd[8 + d];
}

__global__ void scan_kernel(const float* __restrict__ A_log,
                            const float* __restrict__ Dp)
{
    int b = blockIdx.x >> 3;
    int d = ((blockIdx.x & 7) << 5) + threadIdx.x;
    float A[16], h[16];
    #pragma unroll
    for (int n = 0; n < 16; n++) { A[n] = -expf(A_log[d*16 + n]); h[n] = 0.f; }
    float Dd = Dp[d];

    for (int l = 0; l < TT; l++) {
        int pos = b*TT + l;
        float delta = g_delta[pos*256 + d];
        float u     = g_u[pos*256 + d];
        float res   = g_res[pos*256 + d];
        const float4* BC4 = (const float4*)(g_BC + pos*32);
        float4 Bv[4], Cv[4];
        #pragma unroll
        for (int i = 0; i < 4; i++) Bv[i] = __ldg(BC4 + i);
        #pragma unroll
        for (int i = 0; i < 4; i++) Cv[i] = __ldg(BC4 + 4 + i);
        float du = delta * u;
        float y = 0.f;
        const float* Bf = (const float*)Bv;
        const float* Cf = (const float*)Cv;
        #pragma unroll
        for (int n = 0; n < 16; n++) {
            float dA = expf(delta * A[n]);
            h[n] = fmaf(dA, h[n], du * Bf[n]);
            y = fmaf(h[n], Cf[n], y);
        }
        y = fmaf(u, Dd, y);
        y *= res / (1.f + expf(-res));
        g_y[pos*256 + d] = y;
    }
}

__global__ void outproj_kernel(const float* __restrict__ ow,
                               float* __restrict__ out)
{
    __shared__ float s_y[256];
    int pos = blockIdx.x;
    int tid = threadIdx.x;
    s_y[tid]       = g_y[pos*256 + tid];
    s_y[tid + 128] = g_y[pos*256 + tid + 128];
    __syncthreads();
    float a = 0.f;
    const float* wr = ow + tid*256;
    #pragma unroll 4
    for (int k = 0; k < 256; k++) a = fmaf(__ldg(wr + k), s_y[k], a);
    out[pos*128 + tid] = a;
}

// ============================================================
extern "C" void kernel_launch(void* const* d_in, const int* in_sizes, int n_in,
                              void* d_out, int out_size)
{
    (void)in_sizes; (void)n_in; (void)out_size;
    const float* rgb     = (const float*)d_in[0];
    const float* conv_w  = (const float*)d_in[1];
    const float* conv_b  = (const float*)d_in[2];
    const float* bn_g    = (const float*)d_in[3];
    const float* bn_b    = (const float*)d_in[4];
    const float* bn_m    = (const float*)d_in[5];
    const float* bn_v    = (const float*)d_in[6];
    const float* proj_w  = (const float*)d_in[7];
    const float* proj_b  = (const float*)d_in[8];
    const float* m_in_w  = (const float*)d_in[9];
    const float* m_cw    = (const float*)d_in[10];
    const float* m_cb    = (const float*)d_in[11];
    const float* m_xw    = (const float*)d_in[12];
    const float* m_dtw   = (const float*)d_in[13];
    const float* m_dtb   = (const float*)d_in[14];
    const float* m_Alog  = (const float*)d_in[15];
    const float* m_D     = (const float*)d_in[16];
    const float* m_ow    = (const float*)d_in[17];
    float* out = (float*)d_out;

    cudaFuncSetAttribute(conv_mma_kernel,
                         cudaFuncAttributeMaxDynamicSharedMemorySize, CONV_SMEM);

    // wfold + 2 zeros position conv at ncu launch index 5
    wfold_kernel<<<(32*4*32 + 255)/256, 256>>>(conv_w, conv_b, bn_g, bn_b, bn_m, bn_v);
    const int H = (FR*576) / 2;
    zero_pooled_kernel<<<(H + 255)/256, 256>>>(0);
    zero_pooled_kernel<<<(H + 255)/256, 256>>>(H);

    conv_mma_kernel<<<FR*28, 256, CONV_SMEM>>>(rgb);

    proj_inproj_kernel<<<FR, 256>>>(proj_w, proj_b, m_in_w);
    conv1d_xproj_kernel<<<FR, 256>>>(m_cw, m_cb, m_xw, m_dtw, m_dtb);
    scan_kernel<<<32, 32>>>(m_Alog, m_D);
    outproj_kernel<<<FR, 128>>>(m_ow, out);
}

// round 10
// speedup vs baseline: 2.9679x; 1.3458x over previous
#include <cuda_runtime.h>
#include <cuda_bf16.h>
#include <math.h>
#include <stdint.h>

#define BB 4
#define TT 90
#define FR (BB*TT)          // 360 frames
#define HW 224
#define DIN 256

// ---- scratch (device globals; no allocation) ----
__device__ __align__(16) uint4 g_wBv[32*4*32];     // B frags: [kt2][j][lane], 64KB
__device__ float g_biasf[64];
__device__ float g_pooled[FR*576];
__device__ float g_xm[FR*DIN];
__device__ float g_res[FR*DIN];
__device__ float g_u[FR*DIN];
__device__ float g_delta[FR*DIN];
__device__ __align__(16) float g_BC[FR*32];
__device__ float g_y[FR*DIN];

// ================= one-time weight prep =================
__global__ void wfold_kernel(const float* __restrict__ conv_w,
                             const float* __restrict__ conv_b,
                             const float* __restrict__ gma,
                             const float* __restrict__ bta,
                             const float* __restrict__ mean,
                             const float* __restrict__ var)
{
    int idx = blockIdx.x * 256 + threadIdx.x;
    if (idx < 64) {
        float inv = gma[idx] * rsqrtf(var[idx] + 1e-5f);
        g_biasf[idx] = (conv_b[idx] - mean[idx]) * inv + bta[idx];
    }
    if (idx >= 32*4*32) return;
    int kt2  = idx >> 7;
    int j    = (idx >> 5) & 3;
    int lane = idx & 31;
    uint32_t comp[4];
    #pragma unroll
    for (int c = 0; c < 4; c++) {
        int nt = 2*j + (c >> 1); int h = c & 1;
        int n = nt*8 + (lane >> 2);
        int kbase = kt2*16 + h*8 + (lane & 3)*2;
        float inv = gma[n] * rsqrtf(var[n] + 1e-5f);
        float v[2];
        #pragma unroll
        for (int e = 0; e < 2; e++) {
            int k = kbase + e;
            int s = k >> 3, kx = k & 7;
            float val = 0.f;
            if (s < 63 && kx < 7) {
                int p = s / 7, ky = s % 7;
                int kt = p / 3, cc = p % 3;
                val = conv_w[(n*3 + cc)*147 + kt*49 + ky*7 + kx] * inv;
            }
            v[e] = val;
        }
        __nv_bfloat162 pk = __floats2bfloat162_rn(v[0], v[1]);
        comp[c] = *(uint32_t*)&pk;
    }
    g_wBv[idx] = make_uint4(comp[0], comp[1], comp[2], comp[3]);
}

__global__ void zero_pooled_kernel(int off) {
    int i = off + blockIdx.x * 256 + threadIdx.x;
    if (i < FR*576) g_pooled[i] = 0.f;
}

// ================= conv via mma.sync (HMMA) — unchanged from R9 =================
#define SIN_U32ROW 116
#define SMEM_POOL_OFF 45936
#define CONV_SMEM (SMEM_POOL_OFF + 576*4)   // 48,240 B -> 4 CTAs/SM

__device__ __forceinline__ void mma16816(float* c, const uint32_t* a,
                                         uint32_t b0, uint32_t b1) {
    asm volatile(
        "mma.sync.aligned.m16n8k16.row.col.f32.bf16.bf16.f32 "
        "{%0,%1,%2,%3}, {%4,%5,%6,%7}, {%8,%9}, {%0,%1,%2,%3};"
        : "+f"(c[0]), "+f"(c[1]), "+f"(c[2]), "+f"(c[3])
        : "r"(a[0]), "r"(a[1]), "r"(a[2]), "r"(a[3]), "r"(b0), "r"(b1));
}

__global__ __launch_bounds__(256, 4)
void conv_mma_kernel(const float* __restrict__ rgb)
{
    extern __shared__ char sm[];
    const uint32_t* in32 = (const uint32_t*)sm;
    float* s_pool        = (float*)(sm + SMEM_POOL_OFF);

    int blk = blockIdx.x;
    int yp = blk % 28; int frame = blk / 28;
    int t = frame % TT; int b = frame / TT;
    int tid = threadIdx.x;
    int w = tid >> 5; int lane = tid & 31;
    int g = lane >> 2; int q = lane & 3;
    int wm = w & 3;    int nh = w >> 2;

    for (int i = tid; i < 576; i += 256) s_pool[i] = 0.f;

    int rowbase = 8*yp - 3;
    for (int r = w; r < 99; r += 8) {
        int pIdx = r / 11, iy = r % 11;
        int tin = t + pIdx/3 - 1; int c = pIdx % 3;
        int grow = rowbase + iy;
        bool rv = (tin >= 0) && (tin < TT) && (grow >= 0) && (grow < HW);
        const float* src = rgb + (((size_t)(b*TT + tin)*3 + c)*HW + grow)*HW;
        uint32_t* dst = (uint32_t*)sm + (pIdx*11 + iy)*SIN_U32ROW;
        #pragma unroll
        for (int it = 0; it < 4; it++) {
            int x2 = lane + it*32;
            if (x2 < 114) {
                int c0 = 2*x2 - 3, c1 = c0 + 1;
                float v0 = (rv && c0 >= 0 && c0 < HW) ? src[c0] : 0.f;
                float v1 = (rv && c1 >= 0 && c1 < HW) ? src[c1] : 0.f;
                __nv_bfloat162 pk = __floats2bfloat162_rn(v0, v1);
                dst[x2] = *(uint32_t*)&pk;
            }
        }
    }
    __syncthreads();

    int x_lo = wm*16 + g;
    int x_hi = x_lo + 8; if (x_hi > 55) x_hi = 55;
    int blo = 2*x_lo + q;
    int bhi = 2*x_hi + q;

    float acc[2][4][4];
    #pragma unroll
    for (int y = 0; y < 2; y++)
        #pragma unroll
        for (int nt = 0; nt < 4; nt++)
            #pragma unroll
            for (int e = 0; e < 4; e++) acc[y][nt][e] = 0.f;

    const uint4* btab = g_wBv + nh*64 + lane;

    #pragma unroll
    for (int kt2 = 0; kt2 < 32; kt2++) {
        const int s0 = 2*kt2, s1 = s0 + 1;
        const int p0 = s0 / 7, ky0 = s0 - 7*p0;
        const int p1 = s1 / 7, ky1 = s1 - 7*p1;
        const int o0 = (p0*11 + ky0)*SIN_U32ROW;
        const int o1 = (s1 == 63) ? o0 : (p1*11 + ky1)*SIN_U32ROW;

        uint4 B0 = __ldg(btab + kt2*128);
        uint4 B1 = __ldg(btab + kt2*128 + 32);

        uint32_t a0[4], a1[4];
        a0[0] = in32[o0 + blo];        a0[1] = in32[o0 + bhi];
        a0[2] = in32[o1 + blo];        a0[3] = in32[o1 + bhi];
        a1[0] = in32[o0 + 464 + blo];  a1[1] = in32[o0 + 464 + bhi];
        a1[2] = in32[o1 + 464 + blo];  a1[3] = in32[o1 + 464 + bhi];

        mma16816(acc[0][0], a0, B0.x, B0.y);  mma16816(acc[1][0], a1, B0.x, B0.y);
        mma16816(acc[0][1], a0, B0.z, B0.w);  mma16816(acc[1][1], a1, B0.z, B0.w);
        mma16816(acc[0][2], a0, B1.x, B1.y);  mma16816(acc[1][2], a1, B1.x, B1.y);
        mma16816(acc[0][3], a0, B1.z, B1.w);  mma16816(acc[1][3], a1, B1.z, B1.w);
    }

    const float i18 = 1.f/18.f, i19 = 1.f/19.f;
    #pragma unroll
    for (int y = 0; y < 2; y++) {
        int rowg = 2*yp + y;
        float rw = (rowg < 18) ? i18 : i19;
        int roff = (rowg < 18) ? 0 : ((rowg < 37) ? 3 : 6);
        #pragma unroll
        for (int h = 0; h < 2; h++) {
            int x = wm*16 + g + h*8;
            if (x < 56) {
                int xbin = (x < 18) ? 0 : ((x < 37) ? 1 : 2);
                float cw = ((x < 18) ? i18 : i19) * rw;
                #pragma unroll
                for (int nt = 0; nt < 4; nt++) {
                    int ch0 = (nh*4 + nt)*8 + q*2;
                    float v0 = acc[y][nt][h*2]     + __ldg(g_biasf + ch0);
                    float v1 = acc[y][nt][h*2 + 1] + __ldg(g_biasf + ch0 + 1);
                    float g0 = 0.5f*v0*(1.0f + erff(v0*0.70710678118654752f));
                    float g1 = 0.5f*v1*(1.0f + erff(v1*0.70710678118654752f));
                    atomicAdd(&s_pool[ch0*9 + roff + xbin],       g0*cw);
                    atomicAdd(&s_pool[(ch0 + 1)*9 + roff + xbin], g1*cw);
                }
            }
        }
    }
    __syncthreads();
    int base = frame*576;
    for (int i = tid; i < 576; i += 256) atomicAdd(&g_pooled[base + i], s_pool[i]);
}

// ================= Mamba chain — coalesced warp-per-row GEMVs =================
__global__ void proj_inproj_kernel(const float* __restrict__ proj_w,
                                   const float* __restrict__ proj_b,
                                   const float* __restrict__ in_w)
{
    __shared__ float s_p[576];
    __shared__ float s_x[128];
    int pos = blockIdx.x;
    int tid = threadIdx.x;           // 256
    int w = tid >> 5, lane = tid & 31;
    for (int i = tid; i < 576; i += 256) s_p[i] = g_pooled[pos*576 + i];
    __syncthreads();

    // phase 1: 128 rows of proj (K=576), 16 rows per warp, lanes stride K
    #pragma unroll
    for (int rr = 0; rr < 16; rr++) {
        int row = w*16 + rr;
        const float* wr = proj_w + row*576;
        float a = 0.f;
        #pragma unroll
        for (int k = lane; k < 576; k += 32) a = fmaf(__ldg(wr + k), s_p[k], a);
        #pragma unroll
        for (int o = 16; o > 0; o >>= 1) a += __shfl_xor_sync(0xffffffffu, a, o);
        if (lane == 0) s_x[row] = a + __ldg(proj_b + row);
    }
    __syncthreads();

    // phase 2: 512 rows of in_proj (K=128), 64 rows per warp
    #pragma unroll
    for (int rr = 0; rr < 64; rr++) {
        int row = w*64 + rr;
        const float* wr = in_w + row*128;
        float a = 0.f;
        #pragma unroll
        for (int k = lane; k < 128; k += 32) a = fmaf(__ldg(wr + k), s_x[k], a);
        #pragma unroll
        for (int o = 16; o > 0; o >>= 1) a += __shfl_xor_sync(0xffffffffu, a, o);
        if (lane == 0) {
            if (row < 256) g_xm[pos*256 + row] = a;
            else           g_res[pos*256 + (row - 256)] = a;
        }
    }
}

__global__ void conv1d_xproj_kernel(const float* __restrict__ cw,
                                    const float* __restrict__ cb,
                                    const float* __restrict__ xw,
                                    const float* __restrict__ dtw,
                                    const float* __restrict__ dtb)
{
    __shared__ float s_u[256];
    __shared__ float s_xd[40];
    int pos = blockIdx.x; int b = pos / TT; int l = pos % TT;
    int d = threadIdx.x;             // 256
    int w = d >> 5, lane = d & 31;

    float xc = cb[d];
    #pragma unroll
    for (int k = 0; k < 4; k++) {
        int li = l - 3 + k;
        if (li >= 0) xc = fmaf(g_xm[(b*TT + li)*256 + d], cw[d*4 + k], xc);
    }
    float u = xc / (1.f + expf(-xc));
    s_u[d] = u;
    g_u[pos*256 + d] = u;
    __syncthreads();

    // x_proj: 40 rows (K=256), 5 rows per warp, coalesced
    #pragma unroll
    for (int rr = 0; rr < 5; rr++) {
        int row = w*5 + rr;
        const float* wr = xw + row*256;
        float a = 0.f;
        #pragma unroll
        for (int k = lane; k < 256; k += 32) a = fmaf(__ldg(wr + k), s_u[k], a);
        #pragma unroll
        for (int o = 16; o > 0; o >>= 1) a += __shfl_xor_sync(0xffffffffu, a, o);
        if (lane == 0) s_xd[row] = a;
    }
    __syncthreads();

    float dr = dtb[d];
    #pragma unroll
    for (int k = 0; k < 8; k++) dr = fmaf(dtw[d*8 + k], s_xd[k], dr);
    float delta = (dr > 20.f) ? dr : log1pf(expf(dr));
    g_delta[pos*256 + d] = delta;
    if (d < 32) g_BC[pos*32 + d] = s_xd[8 + d];
}

__global__ void scan_kernel(const float* __restrict__ A_log,
                            const float* __restrict__ Dp)
{
    int b = blockIdx.x >> 3;
    int d = ((blockIdx.x & 7) << 5) + threadIdx.x;
    float A[16], h[16];
    #pragma unroll
    for (int n = 0; n < 16; n++) { A[n] = -expf(A_log[d*16 + n]); h[n] = 0.f; }
    float Dd = Dp[d];

    for (int l = 0; l < TT; l++) {
        int pos = b*TT + l;
        float delta = g_delta[pos*256 + d];
        float u     = g_u[pos*256 + d];
        float res   = g_res[pos*256 + d];
        const float4* BC4 = (const float4*)(g_BC + pos*32);
        float4 Bv[4], Cv[4];
        #pragma unroll
        for (int i = 0; i < 4; i++) Bv[i] = __ldg(BC4 + i);
        #pragma unroll
        for (int i = 0; i < 4; i++) Cv[i] = __ldg(BC4 + 4 + i);
        float du = delta * u;
        float y = 0.f;
        const float* Bf = (const float*)Bv;
        const float* Cf = (const float*)Cv;
        #pragma unroll
        for (int n = 0; n < 16; n++) {
            float dA = expf(delta * A[n]);
            h[n] = fmaf(dA, h[n], du * Bf[n]);
            y = fmaf(h[n], Cf[n], y);
        }
        y = fmaf(u, Dd, y);
        y *= res / (1.f + expf(-res));
        g_y[pos*256 + d] = y;
    }
}

__global__ void outproj_kernel(const float* __restrict__ ow,
                               float* __restrict__ out)
{
    __shared__ float s_y[256];
    int pos = blockIdx.x;
    int tid = threadIdx.x;           // 256
    int w = tid >> 5, lane = tid & 31;
    s_y[tid] = g_y[pos*256 + tid];
    __syncthreads();
    // 128 rows (K=256), 16 rows per warp, coalesced
    #pragma unroll
    for (int rr = 0; rr < 16; rr++) {
        int row = w*16 + rr;
        const float* wr = ow + row*256;
        float a = 0.f;
        #pragma unroll
        for (int k = lane; k < 256; k += 32) a = fmaf(__ldg(wr + k), s_y[k], a);
        #pragma unroll
        for (int o = 16; o > 0; o >>= 1) a += __shfl_xor_sync(0xffffffffu, a, o);
        if (lane == 0) out[pos*128 + row] = a;
    }
}

// ============================================================
extern "C" void kernel_launch(void* const* d_in, const int* in_sizes, int n_in,
                              void* d_out, int out_size)
{
    (void)in_sizes; (void)n_in; (void)out_size;
    const float* rgb     = (const float*)d_in[0];
    const float* conv_w  = (const float*)d_in[1];
    const float* conv_b  = (const float*)d_in[2];
    const float* bn_g    = (const float*)d_in[3];
    const float* bn_b    = (const float*)d_in[4];
    const float* bn_m    = (const float*)d_in[5];
    const float* bn_v    = (const float*)d_in[6];
    const float* proj_w  = (const float*)d_in[7];
    const float* proj_b  = (const float*)d_in[8];
    const float* m_in_w  = (const float*)d_in[9];
    const float* m_cw    = (const float*)d_in[10];
    const float* m_cb    = (const float*)d_in[11];
    const float* m_xw    = (const float*)d_in[12];
    const float* m_dtw   = (const float*)d_in[13];
    const float* m_dtb   = (const float*)d_in[14];
    const float* m_Alog  = (const float*)d_in[15];
    const float* m_D     = (const float*)d_in[16];
    const float* m_ow    = (const float*)d_in[17];
    float* out = (float*)d_out;

    cudaFuncSetAttribute(conv_mma_kernel,
                         cudaFuncAttributeMaxDynamicSharedMemorySize, CONV_SMEM);

    // wfold + 2 zeros position conv at ncu launch index 5
    wfold_kernel<<<(32*4*32 + 255)/256, 256>>>(conv_w, conv_b, bn_g, bn_b, bn_m, bn_v);
    const int H = (FR*576) / 2;
    zero_pooled_kernel<<<(H + 255)/256, 256>>>(0);
    zero_pooled_kernel<<<(H + 255)/256, 256>>>(H);

    conv_mma_kernel<<<FR*28, 256, CONV_SMEM>>>(rgb);

    proj_inproj_kernel<<<FR, 256>>>(proj_w, proj_b, m_in_w);
    conv1d_xproj_kernel<<<FR, 256>>>(m_cw, m_cb, m_xw, m_dtw, m_dtb);
    scan_kernel<<<32, 32>>>(m_Alog, m_D);
    outproj_kernel<<<FR, 256>>>(m_ow, out);
}